// round 12
// baseline (speedup 1.0000x reference)
#include <cuda_runtime.h>
#include <cuda_bf16.h>
#include <math.h>
#include <cstdint>

// Problem constants (fixed by reference setup_inputs)
#define BSZ   4096
#define D0    2048
#define D1    128
#define NTOT  8192
#define TM    128
#define NT    (NTOT / TM)            // 64
#define NTILES_TRI (NT * (NT + 1) / 2)  // 2080
#define PERSIST_GRID 296             // 2 CTAs/SM x 148 SMs (co-resident)
#define ROWCHUNK 222                 // ceil(8192/37); grid = 8 colblocks x 37 chunks
// bf16 screen threshold vs exact threshold (margin covers bf16 dot error ~ +-6).
#define SCREEN_T 145.0f
#define EXACT_T  130.0f

#define SPAD1 136                     // smem row stride (bf16 elems): 272B, 16B-aligned
#define QCAP  1024

// dynamic smem layout (bytes)
#define SM_A     0
#define SM_B     (128 * SPAD1 * 2)                  // 34816
#define SM_SQB   (SM_B + 128 * SPAD1 * 2)           // 69632  (2 buffers x 512B)
#define SM_SQA   (SM_SQB + 1024)                    // 70656  (2 buffers x 512B)
#define SM_WRED  (SM_SQA + 1024)                    // 71680  (8 floats)
#define SM_MINB  (SM_WRED + 8 * 4)                  // 71712  (2 floats)
#define SM_QUEUE (SM_MINB + 2 * 4)                  // 71720
#define SM_QCNT  (SM_QUEUE + QCAP * 4)              // 75816
#define SM_TOTAL (SM_QCNT + 32)                     // 75848

// ---- scratch (allocation-free rule: __device__ globals) ----
__device__ float  g_sq0[NTOT];
__device__ float  g_sq1[NTOT];
__device__ float  g_colsum[D0];
__device__ double g_sum_sq0;
__device__ double g_acc;
__device__ float  g_inv_bw[5];
__device__ unsigned g_done_f0;
__device__ unsigned g_done_tile;
__device__ unsigned g_bw_ready;
__device__ __nv_bfloat16 g_x1[(size_t)NTOT * D1];   // bf16 copy of feature1 (2 MB)

__device__ __forceinline__ uint32_t smem_u32(const void* p) {
    uint32_t a;
    asm("{ .reg .u64 t; cvta.to.shared.u64 t, %1; cvt.u32.u64 %0, t; }"
        : "=r"(a) : "l"(p));
    return a;
}

__device__ __forceinline__ void wait_bw_ready() {
    if (atomicAdd(&g_bw_ready, 0u) == 0u) {
        while (atomicAdd(&g_bw_ready, 0u) == 0u) __nanosleep(128);
    }
    __threadfence();
}

// Cold path: exact scalar recompute (queue overflow only; keeps hot regs lean)
__device__ __noinline__ float pair_exact_scalar(
    int aa, int bb,
    const float* __restrict__ src0, const float* __restrict__ tar0,
    const float* __restrict__ src1, const float* __restrict__ tar1)
{
    wait_bw_ready();
    const float* ra1 = (aa < BSZ) ? (src1 + (size_t)aa * D1)
                                  : (tar1 + (size_t)(aa - BSZ) * D1);
    const float* rb1 = (bb < BSZ) ? (src1 + (size_t)bb * D1)
                                  : (tar1 + (size_t)(bb - BSZ) * D1);
    float dp1 = 0.0f;
    for (int dd = 0; dd < D1; dd += 4) {
        float4 x = *(const float4*)(ra1 + dd);
        float4 y = *(const float4*)(rb1 + dd);
        dp1 += x.x * y.x + x.y * y.y + x.z * y.z + x.w * y.w;
    }
    float l21 = g_sq1[aa] + g_sq1[bb] - 2.0f * dp1;
    if (l21 >= EXACT_T) return 0.0f;
    const float* ra0 = (aa < BSZ) ? (src0 + (size_t)aa * D0)
                                  : (tar0 + (size_t)(aa - BSZ) * D0);
    const float* rb0 = (bb < BSZ) ? (src0 + (size_t)bb * D0)
                                  : (tar0 + (size_t)(bb - BSZ) * D0);
    float dp0 = 0.0f;
    for (int dd = 0; dd < D0; dd += 4) {
        float4 x = *(const float4*)(ra0 + dd);
        float4 y = *(const float4*)(rb0 + dd);
        dp0 += x.x * y.x + x.y * y.y + x.z * y.z + x.w * y.w;
    }
    float l20 = g_sq0[aa] + g_sq0[bb] - 2.0f * dp0;
    float k0v = 0.0f;
#pragma unroll
    for (int q = 0; q < 5; q++) k0v += expf(-l20 * g_inv_bw[q]);
    return k0v * expf(-l21 * (1.0f / 1.68f));
}

// ---------------------------------------------------------------------------
// K1: zero accumulators + convert feature1 to bf16 + per-row sq1
// ---------------------------------------------------------------------------
__global__ __launch_bounds__(256) void k_pre(
    const float* __restrict__ src1, const float* __restrict__ tar1)
{
    int bid = blockIdx.x;
    int t = threadIdx.x;
    int w = t >> 5, l = t & 31;

    if (bid < 8)  g_colsum[bid * 256 + t] = 0.0f;
    else if (bid < 40) g_sq0[(bid - 8) * 256 + t] = 0.0f;
    if (bid == 0 && t == 0) {
        g_sum_sq0 = 0.0; g_acc = 0.0;
        g_done_f0 = 0u; g_done_tile = 0u; g_bw_ready = 0u;
    }

    int base = bid * 32 + w * 4;
#pragma unroll
    for (int rr = 0; rr < 4; rr++) {
        int n = base + rr;
        const float* r1 = (n < BSZ) ? (src1 + (size_t)n * D1)
                                    : (tar1 + (size_t)(n - BSZ) * D1);
        float4 v = ((const float4*)r1)[l];
        __nv_bfloat162 lo = __floats2bfloat162_rn(v.x, v.y);
        __nv_bfloat162 hi = __floats2bfloat162_rn(v.z, v.w);
        uint2 pk;
        pk.x = *(uint32_t*)&lo;
        pk.y = *(uint32_t*)&hi;
        *(uint2*)(g_x1 + (size_t)n * D1 + l * 4) = pk;
        float s = v.x * v.x + v.y * v.y + v.z * v.z + v.w * v.w;
#pragma unroll
        for (int off = 16; off; off >>= 1)
            s += __shfl_xor_sync(0xffffffffu, s, off);
        if (l == 0) g_sq1[n] = s;
    }
}

__device__ __forceinline__ void unrank_tri(int idx, int& by, int& bx) {
    int r = (int)((2.0 * NT + 1.0
                   - sqrt((2.0 * NT + 1.0) * (2.0 * NT + 1.0) - 8.0 * idx)) * 0.5);
    if (r < 0) r = 0;
    while (r * NT - r * (r - 1) / 2 > idx) r--;
    while ((r + 1) * NT - (r + 1) * r / 2 <= idx) r++;
    by = r;
    bx = r + (idx - (r * NT - r * (r - 1) / 2));
}

// ---------------------------------------------------------------------------
// K4: persistent kernel. Prologue: fused feature-0 pass (row sq0 + col sums +
// total sq; last CTA finalizes bandwidth, raises g_bw_ready) overlapped with
// the first tile's cp.async prefetch. Main: bf16 HMMA screening GEMM
// (256 thr, 8 warps 4x2, warp tile 32x64, 2 CTAs/SM), fast-path screen,
// queue-based warp-cooperative exact epilogue (spins on g_bw_ready only when
// pairs flagged). Last CTA writes the final scalar.
// ---------------------------------------------------------------------------
__global__ __launch_bounds__(256, 2) void k_tile(
    const float* __restrict__ src0, const float* __restrict__ tar0,
    const float* __restrict__ src1, const float* __restrict__ tar1,
    float* __restrict__ out)
{
    extern __shared__ char dsm[];
    float*    sqbbuf = (float*)(dsm + SM_SQB);      // [2][128]
    float*    sqabuf = (float*)(dsm + SM_SQA);      // [2][128]
    float*    wred   = (float*)(dsm + SM_WRED);
    float*    minb   = (float*)(dsm + SM_MINB);     // [2]
    uint32_t* queue  = (uint32_t*)(dsm + SM_QUEUE);
    uint32_t* qcount = (uint32_t*)(dsm + SM_QCNT);

    int tid = threadIdx.x;
    int wid = tid >> 5, lane = tid & 31;
    int wy = wid >> 1, wx = wid & 1;    // 4x2 warp grid, warp tile 32x64

    uint32_t sAb = smem_u32(dsm + SM_A);
    uint32_t sBb = smem_u32(dsm + SM_B);
    uint32_t sSqB = smem_u32(sqbbuf);
    uint32_t sSqA = smem_u32(sqabuf);

    // fill addressing (invariant)
    int row0 = tid >> 4, cc0 = tid & 15;
    uint32_t dstA0 = sAb + (uint32_t)(row0 * SPAD1 + cc0 * 8) * 2;
    uint32_t dstB0 = sBb + (uint32_t)(row0 * SPAD1 + cc0 * 8) * 2;
    const char* gx = (const char*)g_x1;
    size_t thrOff = ((size_t)row0 * D1 + cc0 * 8) * 2;   // bytes

    uint32_t aRow = (uint32_t)(wy * 32 + (lane & 15));
    uint32_t aKof = (uint32_t)((lane >> 4) * 8);
    uint32_t bRowBase = (uint32_t)(wx * 64 + ((lane >> 3) & 1) * 8 + (lane & 7));
    uint32_t bKof = (uint32_t)((lane >> 4) * 8);
    uint32_t aA0 = sAb + (aRow * SPAD1 + aKof) * 2;
    uint32_t bB0 = sBb + (bRowBase * SPAD1 + bKof) * 2;

    if (tid == 0) *qcount = 0;

    int idx = blockIdx.x;
    int by, bx;
    unrank_tri(idx, by, bx);

    // ---- issue first tile's prefetch BEFORE the f0 pass (overlap) ----
    {
        const char* pa = gx + (size_t)(by * TM) * (D1 * 2) + thrOff;
        const char* pb = gx + (size_t)(bx * TM) * (D1 * 2) + thrOff;
#pragma unroll
        for (int i = 0; i < 8; i++) {
            asm volatile("cp.async.cg.shared.global [%0], [%1], 16;"
                         :: "r"(dstA0 + (uint32_t)(i * 4352)), "l"(pa + i * 4096));
            asm volatile("cp.async.cg.shared.global [%0], [%1], 16;"
                         :: "r"(dstB0 + (uint32_t)(i * 4352)), "l"(pb + i * 4096));
        }
        if (tid < 32) {
            asm volatile("cp.async.ca.shared.global [%0], [%1], 16;"
                         :: "r"(sSqB + (uint32_t)tid * 16),
                            "l"(g_sq1 + bx * TM + tid * 4));
        } else if (tid < 64) {
            asm volatile("cp.async.ca.shared.global [%0], [%1], 16;"
                         :: "r"(sSqA + (uint32_t)(tid - 32) * 16),
                            "l"(g_sq1 + by * TM + (tid - 32) * 4));
        }
        asm volatile("cp.async.commit_group;" ::: "memory");
    }

    // ---- fused feature-0 pass: this CTA's share ----
    {
        int cb = blockIdx.x & 7;             // 8 col-blocks of 256
        int rc = blockIdx.x >> 3;            // 37 row-chunks
        int d4 = cb * 64;                    // float4 col index base
        int rbeg = rc * ROWCHUNK;
        int rend = rbeg + ROWCHUNK; if (rend > NTOT) rend = NTOT;
        float4 ca0 = make_float4(0.f, 0.f, 0.f, 0.f);
        float4 ca1 = make_float4(0.f, 0.f, 0.f, 0.f);
        double wsum = 0.0;
        for (int n = rbeg + wid; n < rend; n += 8) {
            const float4* p4 = (n < BSZ)
                ? (const float4*)(src0 + (size_t)n * D0)
                : (const float4*)(tar0 + (size_t)(n - BSZ) * D0);
            float4 a = p4[d4 + lane];
            float4 b = p4[d4 + 32 + lane];
            ca0.x += a.x; ca0.y += a.y; ca0.z += a.z; ca0.w += a.w;
            ca1.x += b.x; ca1.y += b.y; ca1.z += b.z; ca1.w += b.w;
            float sq = a.x * a.x + a.y * a.y + a.z * a.z + a.w * a.w
                     + b.x * b.x + b.y * b.y + b.z * b.z + b.w * b.w;
#pragma unroll
            for (int off = 16; off; off >>= 1)
                sq += __shfl_xor_sync(0xffffffffu, sq, off);
            if (lane == 0) { atomicAdd(&g_sq0[n], sq); wsum += (double)sq; }
        }
        if (lane == 0) atomicAdd(&g_sum_sq0, wsum);
        int c0 = cb * 256 + lane * 4;
        atomicAdd(&g_colsum[c0 + 0], ca0.x);
        atomicAdd(&g_colsum[c0 + 1], ca0.y);
        atomicAdd(&g_colsum[c0 + 2], ca0.z);
        atomicAdd(&g_colsum[c0 + 3], ca0.w);
        atomicAdd(&g_colsum[c0 + 128], ca1.x);
        atomicAdd(&g_colsum[c0 + 129], ca1.y);
        atomicAdd(&g_colsum[c0 + 130], ca1.z);
        atomicAdd(&g_colsum[c0 + 131], ca1.w);

        __shared__ bool isLast;
        __syncthreads();
        if (tid == 0) {
            __threadfence();
            unsigned o = atomicAdd(&g_done_f0, 1u);
            isLast = (o == PERSIST_GRID - 1u);
        }
        __syncthreads();
        if (isLast) {
            double s = 0.0;
#pragma unroll
            for (int j = 0; j < 8; j++) {
                double c = (double)g_colsum[tid + j * 256];
                s += c * c;
            }
#pragma unroll
            for (int off = 16; off; off >>= 1)
                s += __shfl_xor_sync(0xffffffffu, s, off);
            double* red = (double*)(dsm + SM_QUEUE);   // reuse queue space (pre-loop)
            if ((tid & 31) == 0) red[tid >> 5] = s;
            __syncthreads();
            if (tid == 0) {
                double tot = 0.0;
#pragma unroll
                for (int i = 0; i < 8; i++) tot += red[i];
                double sum_l2 = 2.0 * (double)NTOT * g_sum_sq0 - 2.0 * tot;
                double bw = sum_l2 / ((double)NTOT * (double)NTOT - (double)NTOT) / 4.0;
#pragma unroll
                for (int i = 0; i < 5; i++)
                    g_inv_bw[i] = (float)(1.0 / (bw * (double)(1 << i)));
                __threadfence();
                atomicExch(&g_bw_ready, 1u);
            }
            __syncthreads();   // protect red[] reuse
        }
    }

    // ---- persistent tile loop ----
    int iter = 0;
    for (; idx < NTILES_TRI; idx += PERSIST_GRID, iter++) {
        int buf = iter & 1;
        int arow0 = by * TM, brow0 = bx * TM;
        float* sqb = sqbbuf + buf * 128;
        float* sqa = sqabuf + buf * 128;

        asm volatile("cp.async.wait_group 0;" ::: "memory");
        __syncthreads();

        // per-tile min of sqb (warp 0) -- published by the post-MMA sync
        if (wid == 0) {
            float m = fminf(fminf(sqb[lane], sqb[lane + 32]),
                            fminf(sqb[lane + 64], sqb[lane + 96]));
#pragma unroll
            for (int off = 16; off; off >>= 1)
                m = fminf(m, __shfl_xor_sync(0xffffffffu, m, off));
            if (lane == 0) minb[buf] = m;
        }

        // --- MMA mainloop: 8 K16 steps ---
        float acc[2][8][4];
#pragma unroll
        for (int mt = 0; mt < 2; mt++)
#pragma unroll
            for (int nt = 0; nt < 8; nt++)
#pragma unroll
                for (int v = 0; v < 4; v++) acc[mt][nt][v] = 0.0f;

#pragma unroll
        for (int ks = 0; ks < 8; ks++) {
            uint32_t a[2][4];
#pragma unroll
            for (int mt = 0; mt < 2; mt++) {
                asm volatile(
                    "ldmatrix.sync.aligned.m8n8.x4.shared.b16 {%0,%1,%2,%3}, [%4];"
                    : "=r"(a[mt][0]), "=r"(a[mt][1]), "=r"(a[mt][2]), "=r"(a[mt][3])
                    : "r"(aA0 + (uint32_t)(mt * 4352 + ks * 32)));
            }
            uint32_t b[4][4];
#pragma unroll
            for (int np = 0; np < 4; np++) {
                asm volatile(
                    "ldmatrix.sync.aligned.m8n8.x4.shared.b16 {%0,%1,%2,%3}, [%4];"
                    : "=r"(b[np][0]), "=r"(b[np][1]), "=r"(b[np][2]), "=r"(b[np][3])
                    : "r"(bB0 + (uint32_t)(np * 4352 + ks * 32)));
            }
#pragma unroll
            for (int mt = 0; mt < 2; mt++)
#pragma unroll
                for (int nt = 0; nt < 8; nt++) {
                    uint32_t b0 = b[nt >> 1][(nt & 1)];
                    uint32_t b1 = b[nt >> 1][(nt & 1) + 2];
                    float* c = acc[mt][nt];
                    asm volatile(
                        "mma.sync.aligned.m16n8k16.row.col.f32.bf16.bf16.f32 "
                        "{%0,%1,%2,%3}, {%4,%5,%6,%7}, {%8,%9}, {%0,%1,%2,%3};"
                        : "+f"(c[0]), "+f"(c[1]), "+f"(c[2]), "+f"(c[3])
                        : "r"(a[mt][0]), "r"(a[mt][1]), "r"(a[mt][2]), "r"(a[mt][3]),
                          "r"(b0), "r"(b1));
                }
        }
        __syncthreads();   // A/B consumed; minb[buf] visible

        // --- prefetch next tile (overlaps epilogue) ---
        int nby = 0, nbx = 0;
        {
            int nidx = idx + PERSIST_GRID;
            if (nidx < NTILES_TRI) {
                unrank_tri(nidx, nby, nbx);
                const char* pa = gx + (size_t)(nby * TM) * (D1 * 2) + thrOff;
                const char* pb = gx + (size_t)(nbx * TM) * (D1 * 2) + thrOff;
#pragma unroll
                for (int i = 0; i < 8; i++) {
                    asm volatile("cp.async.cg.shared.global [%0], [%1], 16;"
                                 :: "r"(dstA0 + (uint32_t)(i * 4352)), "l"(pa + i * 4096));
                    asm volatile("cp.async.cg.shared.global [%0], [%1], 16;"
                                 :: "r"(dstB0 + (uint32_t)(i * 4352)), "l"(pb + i * 4096));
                }
                uint32_t nb2 = (uint32_t)(buf ^ 1) * 512;
                if (tid < 32) {
                    asm volatile("cp.async.ca.shared.global [%0], [%1], 16;"
                                 :: "r"(sSqB + nb2 + (uint32_t)tid * 16),
                                    "l"(g_sq1 + nbx * TM + tid * 4));
                } else if (tid < 64) {
                    asm volatile("cp.async.ca.shared.global [%0], [%1], 16;"
                                 :: "r"(sSqA + nb2 + (uint32_t)(tid - 32) * 16),
                                    "l"(g_sq1 + nby * TM + (tid - 32) * 4));
                }
                asm volatile("cp.async.commit_group;" ::: "memory");
            }
        }

        // --- screen with fast-path skip (sqa/sqb from smem strips) ---
        float sqa0 = sqa[wy * 32 + (lane >> 2)];
        float sqa1 = sqa[wy * 32 + (lane >> 2) + 8];
        float sqa2 = sqa[wy * 32 + 16 + (lane >> 2)];
        float sqa3 = sqa[wy * 32 + 16 + (lane >> 2) + 8];

        float local = 0.0f;
        {
            float maxacc = acc[0][0][0];
#pragma unroll
            for (int mt = 0; mt < 2; mt++)
#pragma unroll
                for (int nt = 0; nt < 8; nt++)
#pragma unroll
                    for (int v = 0; v < 4; v++)
                        maxacc = fmaxf(maxacc, acc[mt][nt][v]);
            float minsqa = fminf(fminf(sqa0, sqa1), fminf(sqa2, sqa3));
            bool skip = (minsqa + minb[buf] - 2.0f * maxacc) >= SCREEN_T;
            if (!skip) {
#pragma unroll
                for (int mt = 0; mt < 2; mt++) {
#pragma unroll
                    for (int nt = 0; nt < 8; nt++) {
#pragma unroll
                        for (int v = 0; v < 4; v++) {
                            int arow = wy * 32 + mt * 16 + (lane >> 2) + 8 * (v >> 1);
                            int col  = wx * 64 + nt * 8 + (lane & 3) * 2 + (v & 1);
                            float sqav = mt ? ((v >> 1) ? sqa3 : sqa2)
                                            : ((v >> 1) ? sqa1 : sqa0);
                            float l2s = sqav + sqb[col] - 2.0f * acc[mt][nt][v];
                            if (l2s < SCREEN_T) {
                                int aa = arow0 + arow;
                                int bb = brow0 + col;
                                if (aa == bb) {
                                    local += 5.0f;   // k1=1, k0=5 at l2=0
                                } else {
                                    uint32_t pos = atomicAdd(qcount, 1u);
                                    if (pos < QCAP)
                                        queue[pos] = ((uint32_t)arow << 8) | (uint32_t)col;
                                    else
                                        local += pair_exact_scalar(aa, bb, src0, tar0,
                                                                   src1, tar1);
                                }
                            }
                        }
                    }
                }
            }
        }
        __syncthreads();

        // --- queue: warp-cooperative exact recompute (needs f0 results) ---
        uint32_t cnt = *qcount;
        if (cnt > QCAP) cnt = QCAP;
        if (cnt) wait_bw_ready();
        float wq = 0.0f;
        for (uint32_t q = (uint32_t)wid; q < cnt; q += 8) {
            uint32_t e = queue[q];
            int aa = arow0 + (int)(e >> 8);
            int bb = brow0 + (int)(e & 255u);
            const float* ra1 = (aa < BSZ) ? (src1 + (size_t)aa * D1)
                                          : (tar1 + (size_t)(aa - BSZ) * D1);
            const float* rb1 = (bb < BSZ) ? (src1 + (size_t)bb * D1)
                                          : (tar1 + (size_t)(bb - BSZ) * D1);
            float4 x = ((const float4*)ra1)[lane];
            float4 y = ((const float4*)rb1)[lane];
            float dp1 = x.x * y.x + x.y * y.y + x.z * y.z + x.w * y.w;
#pragma unroll
            for (int off = 16; off; off >>= 1)
                dp1 += __shfl_xor_sync(0xffffffffu, dp1, off);
            float l21 = g_sq1[aa] + g_sq1[bb] - 2.0f * dp1;
            if (l21 < EXACT_T) {
                const float* ra0 = (aa < BSZ) ? (src0 + (size_t)aa * D0)
                                              : (tar0 + (size_t)(aa - BSZ) * D0);
                const float* rb0 = (bb < BSZ) ? (src0 + (size_t)bb * D0)
                                              : (tar0 + (size_t)(bb - BSZ) * D0);
                float dp0 = 0.0f;
#pragma unroll
                for (int it = 0; it < 16; it++) {
                    float4 xx = ((const float4*)ra0)[lane + it * 32];
                    float4 yy = ((const float4*)rb0)[lane + it * 32];
                    dp0 += xx.x * yy.x + xx.y * yy.y + xx.z * yy.z + xx.w * yy.w;
                }
#pragma unroll
                for (int off = 16; off; off >>= 1)
                    dp0 += __shfl_xor_sync(0xffffffffu, dp0, off);
                float l20 = g_sq0[aa] + g_sq0[bb] - 2.0f * dp0;
                float k0v = 0.0f;
#pragma unroll
                for (int qq = 0; qq < 5; qq++)
                    k0v += expf(-l20 * g_inv_bw[qq]);
                if (lane == 0) wq += k0v * expf(-l21 * (1.0f / 1.68f));
            }
        }

        // --- reduce + signed/weighted accumulate ---
#pragma unroll
        for (int off = 16; off; off >>= 1)
            local += __shfl_xor_sync(0xffffffffu, local, off);
        if (lane == 0) wred[wid] = local + wq;
        __syncthreads();
        if (tid == 0) {
            float rsum = 0.0f;
#pragma unroll
            for (int i = 0; i < 8; i++) rsum += wred[i];
            if (rsum != 0.0f) {
                float w   = (bx == by) ? 1.0f : 2.0f;
                float sgn = ((by < NT / 2) == (bx < NT / 2)) ? 1.0f : -1.0f;
                atomicAdd(&g_acc, (double)(rsum * w * sgn));
            }
            *qcount = 0;      // ordered before next screen by the syncs above it
        }
        by = nby; bx = nbx;
    }

    // --- last persistent CTA writes the final scalar (fused k_out) ---
    __syncthreads();
    if (tid == 0) {
        __threadfence();
        unsigned o = atomicAdd(&g_done_tile, 1u);
        if (o == PERSIST_GRID - 1)
            out[0] = (float)(g_acc / ((double)BSZ * (double)BSZ));
    }
}

extern "C" void kernel_launch(void* const* d_in, const int* in_sizes, int n_in,
                              void* d_out, int out_size)
{
    const float* src0 = (const float*)d_in[0];
    const float* src1 = (const float*)d_in[1];
    const float* tar0 = (const float*)d_in[2];
    const float* tar1 = (const float*)d_in[3];
    float* out = (float*)d_out;

    cudaFuncSetAttribute(k_tile, cudaFuncAttributeMaxDynamicSharedMemorySize, SM_TOTAL);

    k_pre<<<256, 256>>>(src1, tar1);
    k_tile<<<PERSIST_GRID, 256, SM_TOTAL>>>(src0, tar0, src1, tar1, out);
}

// round 13
// speedup vs baseline: 2.0900x; 2.0900x over previous
#include <cuda_runtime.h>
#include <cuda_bf16.h>
#include <math.h>
#include <cstdint>

// Problem constants (fixed by reference setup_inputs)
#define BSZ   4096
#define D0    2048
#define D1    128
#define NTOT  8192
#define TM    128
#define NT    (NTOT / TM)            // 64
#define NTILES_TRI (NT * (NT + 1) / 2)  // 2080
#define PERSIST_GRID 296             // 2 CTAs/SM x 148 SMs
// bf16 screen threshold vs exact threshold (margin covers bf16 dot error ~ +-6).
#define SCREEN_T 145.0f
#define EXACT_T  130.0f

#define QCAP  1024
#define BLOB  32768                   // one 128-row x 256B swizzled tile blob

// dynamic smem layout (bytes)
#define SM_A     0
#define SM_B     32768
#define SM_SQB   65536                // 2 buffers x 512B
#define SM_SQA   66560                // 2 buffers x 512B
#define SM_WRED  67584                // 8 floats
#define SM_MINB  67616                // 2 floats
#define SM_MBAR  67624                // 8B mbarrier
#define SM_QUEUE 67632
#define SM_QCNT  (SM_QUEUE + QCAP * 4)   // 71728
#define SM_TOTAL (SM_QCNT + 32)          // 71760

// ---- scratch (allocation-free rule: __device__ globals) ----
__device__ float  g_sq0[NTOT];
__device__ float  g_sq1[NTOT];
__device__ float  g_colsum[D0];
__device__ double g_sum_sq0;
__device__ double g_acc;
__device__ float  g_inv_bw[5];
__device__ unsigned g_done_f0;
__device__ unsigned g_done_tile;
// bf16 copy of feature1, stored as 64 blobs of 128 rows x 256B, chunk-swizzled
__device__ __align__(128) __nv_bfloat16 g_x1[(size_t)NTOT * D1];

__device__ __forceinline__ uint32_t smem_u32(const void* p) {
    uint32_t a;
    asm("{ .reg .u64 t; cvta.to.shared.u64 t, %1; cvt.u32.u64 %0, t; }"
        : "=r"(a) : "l"(p));
    return a;
}

__device__ __forceinline__ void bulk_ld(uint32_t dst, const void* src,
                                        uint32_t bytes, uint32_t mbar) {
    asm volatile(
        "{\n\t.reg .u64 g;\n\tcvta.to.global.u64 g, %1;\n\t"
        "cp.async.bulk.shared::cluster.global.mbarrier::complete_tx::bytes "
        "[%0], [g], %2, [%3];\n\t}"
        :: "r"(dst), "l"(src), "r"(bytes), "r"(mbar) : "memory");
}

__device__ __forceinline__ void mbar_wait(uint32_t mbar, uint32_t parity) {
    asm volatile(
        "{\n\t.reg .pred P;\n\t"
        "WL_%=:\n\t"
        "mbarrier.try_wait.parity.acquire.cta.shared::cta.b64 P, [%0], %1, 0x989680;\n\t"
        "@P bra.uni WD_%=;\n\t"
        "bra.uni WL_%=;\n\t"
        "WD_%=:\n\t}"
        :: "r"(mbar), "r"(parity) : "memory");
}

// Cold path: exact scalar recompute (queue overflow only; keeps hot regs lean)
__device__ __noinline__ float pair_exact_scalar(
    int aa, int bb,
    const float* __restrict__ src0, const float* __restrict__ tar0,
    const float* __restrict__ src1, const float* __restrict__ tar1)
{
    const float* ra1 = (aa < BSZ) ? (src1 + (size_t)aa * D1)
                                  : (tar1 + (size_t)(aa - BSZ) * D1);
    const float* rb1 = (bb < BSZ) ? (src1 + (size_t)bb * D1)
                                  : (tar1 + (size_t)(bb - BSZ) * D1);
    float dp1 = 0.0f;
    for (int dd = 0; dd < D1; dd += 4) {
        float4 x = *(const float4*)(ra1 + dd);
        float4 y = *(const float4*)(rb1 + dd);
        dp1 += x.x * y.x + x.y * y.y + x.z * y.z + x.w * y.w;
    }
    float l21 = g_sq1[aa] + g_sq1[bb] - 2.0f * dp1;
    if (l21 >= EXACT_T) return 0.0f;
    const float* ra0 = (aa < BSZ) ? (src0 + (size_t)aa * D0)
                                  : (tar0 + (size_t)(aa - BSZ) * D0);
    const float* rb0 = (bb < BSZ) ? (src0 + (size_t)bb * D0)
                                  : (tar0 + (size_t)(bb - BSZ) * D0);
    float dp0 = 0.0f;
    for (int dd = 0; dd < D0; dd += 4) {
        float4 x = *(const float4*)(ra0 + dd);
        float4 y = *(const float4*)(rb0 + dd);
        dp0 += x.x * y.x + x.y * y.y + x.z * y.z + x.w * y.w;
    }
    float l20 = g_sq0[aa] + g_sq0[bb] - 2.0f * dp0;
    float k0v = 0.0f;
#pragma unroll
    for (int q = 0; q < 5; q++) k0v += expf(-l20 * g_inv_bw[q]);
    return k0v * expf(-l21 * (1.0f / 1.68f));
}

// ---------------------------------------------------------------------------
// K1: zero accumulators + convert feature1 to bf16 (swizzled blobs) + sq1
// ---------------------------------------------------------------------------
__global__ __launch_bounds__(256) void k_pre(
    const float* __restrict__ src1, const float* __restrict__ tar1)
{
    int bid = blockIdx.x;
    int t = threadIdx.x;
    int w = t >> 5, l = t & 31;

    if (bid < 8)  g_colsum[bid * 256 + t] = 0.0f;
    else if (bid < 40) g_sq0[(bid - 8) * 256 + t] = 0.0f;
    if (bid == 0 && t == 0) {
        g_sum_sq0 = 0.0; g_acc = 0.0;
        g_done_f0 = 0u; g_done_tile = 0u;
    }

    char* gx = (char*)g_x1;
    int base = bid * 32 + w * 4;
#pragma unroll
    for (int rr4 = 0; rr4 < 4; rr4++) {
        int n = base + rr4;
        const float* r1 = (n < BSZ) ? (src1 + (size_t)n * D1)
                                    : (tar1 + (size_t)(n - BSZ) * D1);
        float4 v = ((const float4*)r1)[l];
        __nv_bfloat162 lo = __floats2bfloat162_rn(v.x, v.y);
        __nv_bfloat162 hi = __floats2bfloat162_rn(v.z, v.w);
        uint2 pk;
        pk.x = *(uint32_t*)&lo;
        pk.y = *(uint32_t*)&hi;
        // swizzled blob store: blob n>>7, row rr = n&127, chunk c = l>>1
        int rr = n & 127;
        int c  = l >> 1;
        size_t off = (size_t)(n >> 7) * BLOB + (size_t)rr * 256
                   + (size_t)((c ^ (rr & 7)) << 4) + (size_t)(l & 1) * 8;
        *(uint2*)(gx + off) = pk;
        float s = v.x * v.x + v.y * v.y + v.z * v.z + v.w * v.w;
#pragma unroll
        for (int off2 = 16; off2; off2 >>= 1)
            s += __shfl_xor_sync(0xffffffffu, s, off2);
        if (l == 0) g_sq1[n] = s;
    }
}

// ---------------------------------------------------------------------------
// K2: fused pass over feature0: row sq0 + col sums + total sq; last CTA
// computes bandwidth constants. grid (8, 64).
// ---------------------------------------------------------------------------
__global__ __launch_bounds__(256) void k_f0(
    const float* __restrict__ src0, const float* __restrict__ tar0)
{
    int w = threadIdx.x >> 5, l = threadIdx.x & 31;
    int t = threadIdx.x;
    int d0 = blockIdx.x * 256;
    int nbase = blockIdx.y * 128 + w * 16;
    float colacc[8] = {};
    double wsum = 0.0;
#pragma unroll 2
    for (int rr = 0; rr < 16; rr++) {
        int n = nbase + rr;
        const float* p = (n < BSZ) ? (src0 + (size_t)n * D0)
                                   : (tar0 + (size_t)(n - BSZ) * D0);
        float sq = 0.0f;
#pragma unroll
        for (int j = 0; j < 8; j++) {
            float v = p[d0 + l + j * 32];
            sq += v * v;
            colacc[j] += v;
        }
#pragma unroll
        for (int off = 16; off; off >>= 1)
            sq += __shfl_xor_sync(0xffffffffu, sq, off);
        if (l == 0) { atomicAdd(&g_sq0[n], sq); wsum += (double)sq; }
    }
    if (l == 0) atomicAdd(&g_sum_sq0, wsum);
#pragma unroll
    for (int j = 0; j < 8; j++)
        atomicAdd(&g_colsum[d0 + l + j * 32], colacc[j]);

    __shared__ bool isLast;
    __syncthreads();
    if (t == 0) {
        __threadfence();
        unsigned o = atomicAdd(&g_done_f0, 1u);
        isLast = (o == 8u * 64u - 1u);
    }
    __syncthreads();
    if (isLast) {
        double s = 0.0;
#pragma unroll
        for (int j = 0; j < 8; j++) {
            double c = (double)g_colsum[t + j * 256];
            s += c * c;
        }
#pragma unroll
        for (int off = 16; off; off >>= 1)
            s += __shfl_xor_sync(0xffffffffu, s, off);
        __shared__ double red[8];
        if ((t & 31) == 0) red[t >> 5] = s;
        __syncthreads();
        if (t == 0) {
            double tot = 0.0;
#pragma unroll
            for (int i = 0; i < 8; i++) tot += red[i];
            double sum_l2 = 2.0 * (double)NTOT * g_sum_sq0 - 2.0 * tot;
            double bw = sum_l2 / ((double)NTOT * (double)NTOT - (double)NTOT) / 4.0;
#pragma unroll
            for (int i = 0; i < 5; i++)
                g_inv_bw[i] = (float)(1.0 / (bw * (double)(1 << i)));
        }
    }
}

__device__ __forceinline__ void unrank_tri(int idx, int& by, int& bx) {
    int r = (int)((2.0 * NT + 1.0
                   - sqrt((2.0 * NT + 1.0) * (2.0 * NT + 1.0) - 8.0 * idx)) * 0.5);
    if (r < 0) r = 0;
    while (r * NT - r * (r - 1) / 2 > idx) r--;
    while ((r + 1) * NT - (r + 1) * r / 2 <= idx) r++;
    by = r;
    bx = r + (idx - (r * NT - r * (r - 1) / 2));
}

// ---------------------------------------------------------------------------
// K4: persistent bf16 HMMA screening GEMM. Contiguous row-major tile ranges
// per CTA (A blob reused across a row run). Fills via cp.async.bulk (32KB
// blob per bulk op, mbarrier expect_tx). ldmatrix on chunk-swizzled blobs.
// Fast-path screen + queue exact epilogue. Last CTA writes the scalar.
// ---------------------------------------------------------------------------
__global__ __launch_bounds__(256, 2) void k_tile(
    const float* __restrict__ src0, const float* __restrict__ tar0,
    const float* __restrict__ src1, const float* __restrict__ tar1,
    float* __restrict__ out)
{
    extern __shared__ __align__(128) char dsm[];
    float*    sqbbuf = (float*)(dsm + SM_SQB);      // [2][128]
    float*    sqabuf = (float*)(dsm + SM_SQA);      // [2][128]
    float*    wred   = (float*)(dsm + SM_WRED);
    float*    minb   = (float*)(dsm + SM_MINB);     // [2]
    uint32_t* queue  = (uint32_t*)(dsm + SM_QUEUE);
    uint32_t* qcount = (uint32_t*)(dsm + SM_QCNT);

    int tid = threadIdx.x;
    int wid = tid >> 5, lane = tid & 31;
    int wy = wid >> 1, wx = wid & 1;    // 4x2 warp grid, warp tile 32x64

    uint32_t sAb  = smem_u32(dsm + SM_A);
    uint32_t sBb  = smem_u32(dsm + SM_B);
    uint32_t sSqB = smem_u32(sqbbuf);
    uint32_t sSqA = smem_u32(sqabuf);
    uint32_t mbar = smem_u32(dsm + SM_MBAR);

    // ldmatrix bases: rows in 256B-stride blobs; swizzle value shared by A/B
    uint32_t rA = (uint32_t)(wy * 32 + (lane & 15));
    uint32_t rB = (uint32_t)(wx * 64 + ((lane >> 3) & 1) * 8 + (lane & 7));
    uint32_t preA = sAb + rA * 256;
    uint32_t preB = sBb + rB * 256;
    uint32_t lxor = (uint32_t)(lane & 7);
    uint32_t kbit = (uint32_t)(lane >> 4);

    const char* gx = (const char*)g_x1;

    if (tid == 0) {
        *qcount = 0;
        asm volatile("mbarrier.init.shared.b64 [%0], %1;" :: "r"(mbar), "r"(1u) : "memory");
    }
    __syncthreads();

    // contiguous tile range for this CTA
    int cstart = (int)(((long long)blockIdx.x * NTILES_TRI) / PERSIST_GRID);
    int cend   = (int)(((long long)(blockIdx.x + 1) * NTILES_TRI) / PERSIST_GRID);
    int by, bx;
    unrank_tri(cstart, by, bx);

    // prologue: A + B bulk load, sq strips
    if (tid == 0) {
        asm volatile("mbarrier.arrive.expect_tx.shared.b64 _, [%0], %1;"
                     :: "r"(mbar), "r"(2u * BLOB) : "memory");
        bulk_ld(sAb, gx + (size_t)by * BLOB, BLOB, mbar);
        bulk_ld(sBb, gx + (size_t)bx * BLOB, BLOB, mbar);
    }
    if (tid < 32) {
        asm volatile("cp.async.ca.shared.global [%0], [%1], 16;"
                     :: "r"(sSqB + (uint32_t)tid * 16),
                        "l"(g_sq1 + bx * TM + tid * 4));
    } else if (tid < 64) {
        asm volatile("cp.async.ca.shared.global [%0], [%1], 16;"
                     :: "r"(sSqA + (uint32_t)(tid - 32) * 16),
                        "l"(g_sq1 + by * TM + (tid - 32) * 4));
    }
    asm volatile("cp.async.commit_group;" ::: "memory");

    int it = 0;
    for (int idx = cstart; idx < cend; idx++, it++) {
        int buf = it & 1;
        int arow0 = by * TM, brow0 = bx * TM;
        float* sqb = sqbbuf + buf * 128;
        float* sqa = sqabuf + buf * 128;

        asm volatile("cp.async.wait_group 0;" ::: "memory");
        mbar_wait(mbar, (uint32_t)(it & 1));
        __syncthreads();

        // per-tile min of sqb (warp 0) -- published by the post-MMA sync
        if (wid == 0) {
            float m = fminf(fminf(sqb[lane], sqb[lane + 32]),
                            fminf(sqb[lane + 64], sqb[lane + 96]));
#pragma unroll
            for (int off = 16; off; off >>= 1)
                m = fminf(m, __shfl_xor_sync(0xffffffffu, m, off));
            if (lane == 0) minb[buf] = m;
        }

        // --- MMA mainloop: 8 K16 steps ---
        float acc[2][8][4];
#pragma unroll
        for (int mt = 0; mt < 2; mt++)
#pragma unroll
            for (int nt = 0; nt < 8; nt++)
#pragma unroll
                for (int v = 0; v < 4; v++) acc[mt][nt][v] = 0.0f;

#pragma unroll
        for (int ks = 0; ks < 8; ks++) {
            uint32_t sw = (((uint32_t)(2 * ks) + kbit) ^ lxor) << 4;
            uint32_t a[2][4];
#pragma unroll
            for (int mt = 0; mt < 2; mt++) {
                asm volatile(
                    "ldmatrix.sync.aligned.m8n8.x4.shared.b16 {%0,%1,%2,%3}, [%4];"
                    : "=r"(a[mt][0]), "=r"(a[mt][1]), "=r"(a[mt][2]), "=r"(a[mt][3])
                    : "r"(preA + (uint32_t)(mt * 4096) + sw));
            }
            uint32_t b[4][4];
#pragma unroll
            for (int np = 0; np < 4; np++) {
                asm volatile(
                    "ldmatrix.sync.aligned.m8n8.x4.shared.b16 {%0,%1,%2,%3}, [%4];"
                    : "=r"(b[np][0]), "=r"(b[np][1]), "=r"(b[np][2]), "=r"(b[np][3])
                    : "r"(preB + (uint32_t)(np * 4096) + sw));
            }
#pragma unroll
            for (int mt = 0; mt < 2; mt++)
#pragma unroll
                for (int nt = 0; nt < 8; nt++) {
                    uint32_t b0 = b[nt >> 1][(nt & 1)];
                    uint32_t b1 = b[nt >> 1][(nt & 1) + 2];
                    float* c = acc[mt][nt];
                    asm volatile(
                        "mma.sync.aligned.m16n8k16.row.col.f32.bf16.bf16.f32 "
                        "{%0,%1,%2,%3}, {%4,%5,%6,%7}, {%8,%9}, {%0,%1,%2,%3};"
                        : "+f"(c[0]), "+f"(c[1]), "+f"(c[2]), "+f"(c[3])
                        : "r"(a[mt][0]), "r"(a[mt][1]), "r"(a[mt][2]), "r"(a[mt][3]),
                          "r"(b0), "r"(b1));
                }
        }
        __syncthreads();   // A/B consumed; minb[buf] visible

        // --- issue next tile's loads (overlaps epilogue) ---
        int nby = by, nbx = bx;
        if (idx + 1 < cend) {
            nbx = bx + 1;
            if (nbx == NT) { nby = by + 1; nbx = nby; }
            if (tid == 0) {
                uint32_t tx = (nby != by) ? 2u * BLOB : BLOB;
                asm volatile("mbarrier.arrive.expect_tx.shared.b64 _, [%0], %1;"
                             :: "r"(mbar), "r"(tx) : "memory");
                if (nby != by)
                    bulk_ld(sAb, gx + (size_t)nby * BLOB, BLOB, mbar);
                bulk_ld(sBb, gx + (size_t)nbx * BLOB, BLOB, mbar);
            }
            uint32_t nb2 = (uint32_t)(buf ^ 1) * 512;
            if (tid < 32) {
                asm volatile("cp.async.ca.shared.global [%0], [%1], 16;"
                             :: "r"(sSqB + nb2 + (uint32_t)tid * 16),
                                "l"(g_sq1 + nbx * TM + tid * 4));
            } else if (tid < 64) {
                asm volatile("cp.async.ca.shared.global [%0], [%1], 16;"
                             :: "r"(sSqA + nb2 + (uint32_t)(tid - 32) * 16),
                                "l"(g_sq1 + nby * TM + (tid - 32) * 4));
            }
            asm volatile("cp.async.commit_group;" ::: "memory");
        }

        // --- screen with fast-path skip ---
        float sqa0 = sqa[wy * 32 + (lane >> 2)];
        float sqa1 = sqa[wy * 32 + (lane >> 2) + 8];
        float sqa2 = sqa[wy * 32 + 16 + (lane >> 2)];
        float sqa3 = sqa[wy * 32 + 16 + (lane >> 2) + 8];

        float local = 0.0f;
        {
            float maxacc = acc[0][0][0];
#pragma unroll
            for (int mt = 0; mt < 2; mt++)
#pragma unroll
                for (int nt = 0; nt < 8; nt++)
#pragma unroll
                    for (int v = 0; v < 4; v++)
                        maxacc = fmaxf(maxacc, acc[mt][nt][v]);
            float minsqa = fminf(fminf(sqa0, sqa1), fminf(sqa2, sqa3));
            bool skip = (minsqa + minb[buf] - 2.0f * maxacc) >= SCREEN_T;
            if (!skip) {
#pragma unroll
                for (int mt = 0; mt < 2; mt++) {
#pragma unroll
                    for (int nt = 0; nt < 8; nt++) {
#pragma unroll
                        for (int v = 0; v < 4; v++) {
                            int arow = wy * 32 + mt * 16 + (lane >> 2) + 8 * (v >> 1);
                            int col  = wx * 64 + nt * 8 + (lane & 3) * 2 + (v & 1);
                            float sqav = mt ? ((v >> 1) ? sqa3 : sqa2)
                                            : ((v >> 1) ? sqa1 : sqa0);
                            float l2s = sqav + sqb[col] - 2.0f * acc[mt][nt][v];
                            if (l2s < SCREEN_T) {
                                int aa = arow0 + arow;
                                int bb = brow0 + col;
                                if (aa == bb) {
                                    local += 5.0f;   // k1=1, k0=5 at l2=0
                                } else {
                                    uint32_t pos = atomicAdd(qcount, 1u);
                                    if (pos < QCAP)
                                        queue[pos] = ((uint32_t)arow << 8) | (uint32_t)col;
                                    else
                                        local += pair_exact_scalar(aa, bb, src0, tar0,
                                                                   src1, tar1);
                                }
                            }
                        }
                    }
                }
            }
        }
        __syncthreads();

        // --- queue: warp-cooperative exact recompute ---
        uint32_t cnt = *qcount;
        if (cnt > QCAP) cnt = QCAP;
        float wq = 0.0f;
        for (uint32_t q = (uint32_t)wid; q < cnt; q += 8) {
            uint32_t e = queue[q];
            int aa = arow0 + (int)(e >> 8);
            int bb = brow0 + (int)(e & 255u);
            const float* ra1 = (aa < BSZ) ? (src1 + (size_t)aa * D1)
                                          : (tar1 + (size_t)(aa - BSZ) * D1);
            const float* rb1 = (bb < BSZ) ? (src1 + (size_t)bb * D1)
                                          : (tar1 + (size_t)(bb - BSZ) * D1);
            float4 x = ((const float4*)ra1)[lane];
            float4 y = ((const float4*)rb1)[lane];
            float dp1 = x.x * y.x + x.y * y.y + x.z * y.z + x.w * y.w;
#pragma unroll
            for (int off = 16; off; off >>= 1)
                dp1 += __shfl_xor_sync(0xffffffffu, dp1, off);
            float l21 = g_sq1[aa] + g_sq1[bb] - 2.0f * dp1;
            if (l21 < EXACT_T) {
                const float* ra0 = (aa < BSZ) ? (src0 + (size_t)aa * D0)
                                              : (tar0 + (size_t)(aa - BSZ) * D0);
                const float* rb0 = (bb < BSZ) ? (src0 + (size_t)bb * D0)
                                              : (tar0 + (size_t)(bb - BSZ) * D0);
                float dp0 = 0.0f;
#pragma unroll
                for (int itn = 0; itn < 16; itn++) {
                    float4 xx = ((const float4*)ra0)[lane + itn * 32];
                    float4 yy = ((const float4*)rb0)[lane + itn * 32];
                    dp0 += xx.x * yy.x + xx.y * yy.y + xx.z * yy.z + xx.w * yy.w;
                }
#pragma unroll
                for (int off = 16; off; off >>= 1)
                    dp0 += __shfl_xor_sync(0xffffffffu, dp0, off);
                float l20 = g_sq0[aa] + g_sq0[bb] - 2.0f * dp0;
                float k0v = 0.0f;
#pragma unroll
                for (int qq = 0; qq < 5; qq++)
                    k0v += expf(-l20 * g_inv_bw[qq]);
                if (lane == 0) wq += k0v * expf(-l21 * (1.0f / 1.68f));
            }
        }

        // --- reduce + signed/weighted accumulate ---
#pragma unroll
        for (int off = 16; off; off >>= 1)
            local += __shfl_xor_sync(0xffffffffu, local, off);
        if (lane == 0) wred[wid] = local + wq;
        __syncthreads();
        if (tid == 0) {
            float rsum = 0.0f;
#pragma unroll
            for (int i = 0; i < 8; i++) rsum += wred[i];
            if (rsum != 0.0f) {
                float w   = (bx == by) ? 1.0f : 2.0f;
                float sgn = ((by < NT / 2) == (bx < NT / 2)) ? 1.0f : -1.0f;
                atomicAdd(&g_acc, (double)(rsum * w * sgn));
            }
            *qcount = 0;      // ordered before next screen by the syncs above it
        }
        by = nby; bx = nbx;
    }

    // --- last persistent CTA writes the final scalar (fused k_out) ---
    __syncthreads();
    if (tid == 0) {
        __threadfence();
        unsigned o = atomicAdd(&g_done_tile, 1u);
        if (o == PERSIST_GRID - 1)
            out[0] = (float)(g_acc / ((double)BSZ * (double)BSZ));
    }
}

extern "C" void kernel_launch(void* const* d_in, const int* in_sizes, int n_in,
                              void* d_out, int out_size)
{
    const float* src0 = (const float*)d_in[0];
    const float* src1 = (const float*)d_in[1];
    const float* tar0 = (const float*)d_in[2];
    const float* tar1 = (const float*)d_in[3];
    float* out = (float*)d_out;

    cudaFuncSetAttribute(k_tile, cudaFuncAttributeMaxDynamicSharedMemorySize, SM_TOTAL);

    k_pre<<<256, 256>>>(src1, tar1);
    k_f0<<<dim3(8, 64), 256>>>(src0, tar0);
    k_tile<<<PERSIST_GRID, 256, SM_TOTAL>>>(src0, tar0, src1, tar1, out);
}

// round 14
// speedup vs baseline: 2.1167x; 1.0128x over previous
#include <cuda_runtime.h>
#include <cuda_bf16.h>
#include <math.h>
#include <cstdint>

// Problem constants (fixed by reference setup_inputs)
#define BSZ   4096
#define D0    2048
#define D1    128
#define NTOT  8192
#define TM    128
#define NT    (NTOT / TM)            // 64
#define NTILES_TRI (NT * (NT + 1) / 2)  // 2080
#define PERSIST_GRID 296             // 2 CTAs/SM x 148 SMs
// bf16 screen threshold vs exact threshold (margin covers bf16 dot error ~ +-6).
#define SCREEN_T 145.0f
#define EXACT_T  130.0f

#define QCAP  1024
#define BLOB  32768                   // one 128-row x 256B swizzled tile blob

// dynamic smem layout (bytes)
#define SM_A     0
#define SM_B     32768                // TWO B buffers (2 x 32KB)
#define SM_SQB   98304                // 2 buffers x 512B
#define SM_SQA   99328                // 2 buffers x 512B
#define SM_WRED  100352               // 8 floats
#define SM_MINB  100384               // 2 floats
#define SM_MBAR  100392               // 2 x 8B mbarriers
#define SM_QUEUE 100408
#define SM_QCNT  (SM_QUEUE + QCAP * 4)   // 104504
#define SM_TOTAL (SM_QCNT + 32)          // 104536

// ---- scratch (allocation-free rule: __device__ globals) ----
__device__ float  g_sq0[NTOT];
__device__ float  g_sq1[NTOT];
__device__ float  g_colsum[D0];
__device__ double g_sum_sq0;
__device__ double g_acc;
__device__ float  g_inv_bw[5];
__device__ unsigned g_done_f0;
__device__ unsigned g_done_tile;
// bf16 copy of feature1, stored as 64 blobs of 128 rows x 256B, chunk-swizzled
__device__ __align__(128) __nv_bfloat16 g_x1[(size_t)NTOT * D1];

__device__ __forceinline__ uint32_t smem_u32(const void* p) {
    uint32_t a;
    asm("{ .reg .u64 t; cvta.to.shared.u64 t, %1; cvt.u32.u64 %0, t; }"
        : "=r"(a) : "l"(p));
    return a;
}

__device__ __forceinline__ void bulk_ld(uint32_t dst, const void* src,
                                        uint32_t bytes, uint32_t mbar) {
    asm volatile(
        "{\n\t.reg .u64 g;\n\tcvta.to.global.u64 g, %1;\n\t"
        "cp.async.bulk.shared::cluster.global.mbarrier::complete_tx::bytes "
        "[%0], [g], %2, [%3];\n\t}"
        :: "r"(dst), "l"(src), "r"(bytes), "r"(mbar) : "memory");
}

__device__ __forceinline__ void mbar_wait(uint32_t mbar, uint32_t parity) {
    asm volatile(
        "{\n\t.reg .pred P;\n\t"
        "WL_%=:\n\t"
        "mbarrier.try_wait.parity.acquire.cta.shared::cta.b64 P, [%0], %1, 0x989680;\n\t"
        "@P bra.uni WD_%=;\n\t"
        "bra.uni WL_%=;\n\t"
        "WD_%=:\n\t}"
        :: "r"(mbar), "r"(parity) : "memory");
}

// Cold path: exact scalar recompute (queue overflow only; keeps hot regs lean)
__device__ __noinline__ float pair_exact_scalar(
    int aa, int bb,
    const float* __restrict__ src0, const float* __restrict__ tar0,
    const float* __restrict__ src1, const float* __restrict__ tar1)
{
    const float* ra1 = (aa < BSZ) ? (src1 + (size_t)aa * D1)
                                  : (tar1 + (size_t)(aa - BSZ) * D1);
    const float* rb1 = (bb < BSZ) ? (src1 + (size_t)bb * D1)
                                  : (tar1 + (size_t)(bb - BSZ) * D1);
    float dp1 = 0.0f;
    for (int dd = 0; dd < D1; dd += 4) {
        float4 x = *(const float4*)(ra1 + dd);
        float4 y = *(const float4*)(rb1 + dd);
        dp1 += x.x * y.x + x.y * y.y + x.z * y.z + x.w * y.w;
    }
    float l21 = g_sq1[aa] + g_sq1[bb] - 2.0f * dp1;
    if (l21 >= EXACT_T) return 0.0f;
    const float* ra0 = (aa < BSZ) ? (src0 + (size_t)aa * D0)
                                  : (tar0 + (size_t)(aa - BSZ) * D0);
    const float* rb0 = (bb < BSZ) ? (src0 + (size_t)bb * D0)
                                  : (tar0 + (size_t)(bb - BSZ) * D0);
    float dp0 = 0.0f;
    for (int dd = 0; dd < D0; dd += 4) {
        float4 x = *(const float4*)(ra0 + dd);
        float4 y = *(const float4*)(rb0 + dd);
        dp0 += x.x * y.x + x.y * y.y + x.z * y.z + x.w * y.w;
    }
    float l20 = g_sq0[aa] + g_sq0[bb] - 2.0f * dp0;
    float k0v = 0.0f;
#pragma unroll
    for (int q = 0; q < 5; q++) k0v += expf(-l20 * g_inv_bw[q]);
    return k0v * expf(-l21 * (1.0f / 1.68f));
}

// ---------------------------------------------------------------------------
// K1: zero accumulators + convert feature1 to bf16 (swizzled blobs) + sq1
// ---------------------------------------------------------------------------
__global__ __launch_bounds__(256) void k_pre(
    const float* __restrict__ src1, const float* __restrict__ tar1)
{
    int bid = blockIdx.x;
    int t = threadIdx.x;
    int w = t >> 5, l = t & 31;

    if (bid < 8)  g_colsum[bid * 256 + t] = 0.0f;
    else if (bid < 40) g_sq0[(bid - 8) * 256 + t] = 0.0f;
    if (bid == 0 && t == 0) {
        g_sum_sq0 = 0.0; g_acc = 0.0;
        g_done_f0 = 0u; g_done_tile = 0u;
    }

    char* gx = (char*)g_x1;
    int base = bid * 32 + w * 4;
#pragma unroll
    for (int rr4 = 0; rr4 < 4; rr4++) {
        int n = base + rr4;
        const float* r1 = (n < BSZ) ? (src1 + (size_t)n * D1)
                                    : (tar1 + (size_t)(n - BSZ) * D1);
        float4 v = ((const float4*)r1)[l];
        __nv_bfloat162 lo = __floats2bfloat162_rn(v.x, v.y);
        __nv_bfloat162 hi = __floats2bfloat162_rn(v.z, v.w);
        uint2 pk;
        pk.x = *(uint32_t*)&lo;
        pk.y = *(uint32_t*)&hi;
        // swizzled blob store: blob n>>7, row rr = n&127, chunk c = l>>1
        int rr = n & 127;
        int c  = l >> 1;
        size_t off = (size_t)(n >> 7) * BLOB + (size_t)rr * 256
                   + (size_t)((c ^ (rr & 7)) << 4) + (size_t)(l & 1) * 8;
        *(uint2*)(gx + off) = pk;
        float s = v.x * v.x + v.y * v.y + v.z * v.z + v.w * v.w;
#pragma unroll
        for (int off2 = 16; off2; off2 >>= 1)
            s += __shfl_xor_sync(0xffffffffu, s, off2);
        if (l == 0) g_sq1[n] = s;
    }
}

// ---------------------------------------------------------------------------
// K2: fused pass over feature0: row sq0 + col sums + total sq; last CTA
// computes bandwidth constants. grid (8, 64).
// ---------------------------------------------------------------------------
__global__ __launch_bounds__(256) void k_f0(
    const float* __restrict__ src0, const float* __restrict__ tar0)
{
    int w = threadIdx.x >> 5, l = threadIdx.x & 31;
    int t = threadIdx.x;
    int d0 = blockIdx.x * 256;
    int nbase = blockIdx.y * 128 + w * 16;
    float colacc[8] = {};
    double wsum = 0.0;
#pragma unroll 2
    for (int rr = 0; rr < 16; rr++) {
        int n = nbase + rr;
        const float* p = (n < BSZ) ? (src0 + (size_t)n * D0)
                                   : (tar0 + (size_t)(n - BSZ) * D0);
        float sq = 0.0f;
#pragma unroll
        for (int j = 0; j < 8; j++) {
            float v = p[d0 + l + j * 32];
            sq += v * v;
            colacc[j] += v;
        }
#pragma unroll
        for (int off = 16; off; off >>= 1)
            sq += __shfl_xor_sync(0xffffffffu, sq, off);
        if (l == 0) { atomicAdd(&g_sq0[n], sq); wsum += (double)sq; }
    }
    if (l == 0) atomicAdd(&g_sum_sq0, wsum);
#pragma unroll
    for (int j = 0; j < 8; j++)
        atomicAdd(&g_colsum[d0 + l + j * 32], colacc[j]);

    __shared__ bool isLast;
    __syncthreads();
    if (t == 0) {
        __threadfence();
        unsigned o = atomicAdd(&g_done_f0, 1u);
        isLast = (o == 8u * 64u - 1u);
    }
    __syncthreads();
    if (isLast) {
        double s = 0.0;
#pragma unroll
        for (int j = 0; j < 8; j++) {
            double c = (double)g_colsum[t + j * 256];
            s += c * c;
        }
#pragma unroll
        for (int off = 16; off; off >>= 1)
            s += __shfl_xor_sync(0xffffffffu, s, off);
        __shared__ double red[8];
        if ((t & 31) == 0) red[t >> 5] = s;
        __syncthreads();
        if (t == 0) {
            double tot = 0.0;
#pragma unroll
            for (int i = 0; i < 8; i++) tot += red[i];
            double sum_l2 = 2.0 * (double)NTOT * g_sum_sq0 - 2.0 * tot;
            double bw = sum_l2 / ((double)NTOT * (double)NTOT - (double)NTOT) / 4.0;
#pragma unroll
            for (int i = 0; i < 5; i++)
                g_inv_bw[i] = (float)(1.0 / (bw * (double)(1 << i)));
        }
    }
}

__device__ __forceinline__ void unrank_tri(int idx, int& by, int& bx) {
    int r = (int)((2.0 * NT + 1.0
                   - sqrt((2.0 * NT + 1.0) * (2.0 * NT + 1.0) - 8.0 * idx)) * 0.5);
    if (r < 0) r = 0;
    while (r * NT - r * (r - 1) / 2 > idx) r--;
    while ((r + 1) * NT - (r + 1) * r / 2 <= idx) r++;
    by = r;
    bx = r + (idx - (r * NT - r * (r - 1) / 2));
}

// ---------------------------------------------------------------------------
// K4: persistent bf16 HMMA screening GEMM. Contiguous row-major tile ranges
// per CTA (A blob reused across a row run). DOUBLE-BUFFERED B: B(i+1) bulk
// issues before MMA(i), hiding the full load latency behind MMA+screen.
// A reloads post-MMA on row changes only. Fast-path screen + queue epilogue.
// ---------------------------------------------------------------------------
__global__ __launch_bounds__(256, 2) void k_tile(
    const float* __restrict__ src0, const float* __restrict__ tar0,
    const float* __restrict__ src1, const float* __restrict__ tar1,
    float* __restrict__ out)
{
    extern __shared__ __align__(128) char dsm[];
    float*    sqbbuf = (float*)(dsm + SM_SQB);      // [2][128]
    float*    sqabuf = (float*)(dsm + SM_SQA);      // [2][128]
    float*    wred   = (float*)(dsm + SM_WRED);
    float*    minb   = (float*)(dsm + SM_MINB);     // [2]
    uint32_t* queue  = (uint32_t*)(dsm + SM_QUEUE);
    uint32_t* qcount = (uint32_t*)(dsm + SM_QCNT);

    int tid = threadIdx.x;
    int wid = tid >> 5, lane = tid & 31;
    int wy = wid >> 1, wx = wid & 1;    // 4x2 warp grid, warp tile 32x64

    uint32_t sAb   = smem_u32(dsm + SM_A);
    uint32_t sBb   = smem_u32(dsm + SM_B);          // base of buffer 0
    uint32_t sSqB  = smem_u32(sqbbuf);
    uint32_t sSqA  = smem_u32(sqabuf);
    uint32_t mbar0 = smem_u32(dsm + SM_MBAR);       // mbar0, mbar0+8

    uint32_t rA = (uint32_t)(wy * 32 + (lane & 15));
    uint32_t rB = (uint32_t)(wx * 64 + ((lane >> 3) & 1) * 8 + (lane & 7));
    uint32_t preA  = sAb + rA * 256;
    uint32_t preB0 = sBb + rB * 256;
    uint32_t lxor = (uint32_t)(lane & 7);
    uint32_t kbit = (uint32_t)(lane >> 4);

    const char* gx = (const char*)g_x1;

    if (tid == 0) {
        *qcount = 0;
        asm volatile("mbarrier.init.shared.b64 [%0], %1;" :: "r"(mbar0), "r"(1u) : "memory");
        asm volatile("mbarrier.init.shared.b64 [%0], %1;" :: "r"(mbar0 + 8), "r"(1u) : "memory");
    }
    __syncthreads();

    // contiguous tile range for this CTA
    int cstart = (int)(((long long)blockIdx.x * NTILES_TRI) / PERSIST_GRID);
    int cend   = (int)(((long long)(blockIdx.x + 1) * NTILES_TRI) / PERSIST_GRID);
    int by, bx;
    unrank_tri(cstart, by, bx);

    // prologue: A + B(0) into buffer 0, sq strips into strip 0
    if (tid == 0) {
        asm volatile("mbarrier.arrive.expect_tx.shared.b64 _, [%0], %1;"
                     :: "r"(mbar0), "r"(2u * BLOB) : "memory");
        bulk_ld(sAb, gx + (size_t)by * BLOB, BLOB, mbar0);
        bulk_ld(sBb, gx + (size_t)bx * BLOB, BLOB, mbar0);
    }
    if (tid < 32) {
        asm volatile("cp.async.ca.shared.global [%0], [%1], 16;"
                     :: "r"(sSqB + (uint32_t)tid * 16),
                        "l"(g_sq1 + bx * TM + tid * 4));
    } else if (tid < 64) {
        asm volatile("cp.async.ca.shared.global [%0], [%1], 16;"
                     :: "r"(sSqA + (uint32_t)(tid - 32) * 16),
                        "l"(g_sq1 + by * TM + (tid - 32) * 4));
    }
    asm volatile("cp.async.commit_group;" ::: "memory");

    int it = 0;
    for (int idx = cstart; idx < cend; idx++, it++) {
        int buf = it & 1;
        int arow0 = by * TM, brow0 = bx * TM;
        float* sqb = sqbbuf + buf * 128;
        float* sqa = sqabuf + buf * 128;
        uint32_t mbar = mbar0 + (uint32_t)buf * 8;
        uint32_t preB = preB0 + (uint32_t)buf * BLOB;

        asm volatile("cp.async.wait_group 0;" ::: "memory");
        mbar_wait(mbar, (uint32_t)((it >> 1) & 1));
        __syncthreads();

        // --- pre-MMA: issue B(i+1) into buf^1 + next sq strips (overlap MMA) ---
        int nby = by, nbx = bx;
        bool have_next = (idx + 1 < cend);
        bool rowchg = false;
        if (have_next) {
            nbx = bx + 1;
            if (nbx == NT) { nby = by + 1; nbx = nby; rowchg = true; }
            if (tid == 0) {
                asm volatile("fence.proxy.async.shared::cta;" ::: "memory");
                uint32_t tx = rowchg ? 2u * BLOB : BLOB;
                asm volatile("mbarrier.arrive.expect_tx.shared.b64 _, [%0], %1;"
                             :: "r"(mbar0 + (uint32_t)(buf ^ 1) * 8), "r"(tx) : "memory");
                bulk_ld(sBb + (uint32_t)(buf ^ 1) * BLOB,
                        gx + (size_t)nbx * BLOB, BLOB,
                        mbar0 + (uint32_t)(buf ^ 1) * 8);
            }
            uint32_t nb2 = (uint32_t)(buf ^ 1) * 512;
            if (tid < 32) {
                asm volatile("cp.async.ca.shared.global [%0], [%1], 16;"
                             :: "r"(sSqB + nb2 + (uint32_t)tid * 16),
                                "l"(g_sq1 + nbx * TM + tid * 4));
            } else if (tid < 64) {
                asm volatile("cp.async.ca.shared.global [%0], [%1], 16;"
                             :: "r"(sSqA + nb2 + (uint32_t)(tid - 32) * 16),
                                "l"(g_sq1 + nby * TM + (tid - 32) * 4));
            }
            asm volatile("cp.async.commit_group;" ::: "memory");
        }

        // per-tile min of sqb (warp 0) -- published by the post-MMA sync
        if (wid == 0) {
            float m = fminf(fminf(sqb[lane], sqb[lane + 32]),
                            fminf(sqb[lane + 64], sqb[lane + 96]));
#pragma unroll
            for (int off = 16; off; off >>= 1)
                m = fminf(m, __shfl_xor_sync(0xffffffffu, m, off));
            if (lane == 0) minb[buf] = m;
        }

        // --- MMA mainloop: 8 K16 steps ---
        float acc[2][8][4];
#pragma unroll
        for (int mt = 0; mt < 2; mt++)
#pragma unroll
            for (int nt = 0; nt < 8; nt++)
#pragma unroll
                for (int v = 0; v < 4; v++) acc[mt][nt][v] = 0.0f;

#pragma unroll
        for (int ks = 0; ks < 8; ks++) {
            uint32_t sw = (((uint32_t)(2 * ks) + kbit) ^ lxor) << 4;
            uint32_t a[2][4];
#pragma unroll
            for (int mt = 0; mt < 2; mt++) {
                asm volatile(
                    "ldmatrix.sync.aligned.m8n8.x4.shared.b16 {%0,%1,%2,%3}, [%4];"
                    : "=r"(a[mt][0]), "=r"(a[mt][1]), "=r"(a[mt][2]), "=r"(a[mt][3])
                    : "r"(preA + (uint32_t)(mt * 4096) + sw));
            }
            uint32_t b[4][4];
#pragma unroll
            for (int np = 0; np < 4; np++) {
                asm volatile(
                    "ldmatrix.sync.aligned.m8n8.x4.shared.b16 {%0,%1,%2,%3}, [%4];"
                    : "=r"(b[np][0]), "=r"(b[np][1]), "=r"(b[np][2]), "=r"(b[np][3])
                    : "r"(preB + (uint32_t)(np * 4096) + sw));
            }
#pragma unroll
            for (int mt = 0; mt < 2; mt++)
#pragma unroll
                for (int nt = 0; nt < 8; nt++) {
                    uint32_t b0 = b[nt >> 1][(nt & 1)];
                    uint32_t b1 = b[nt >> 1][(nt & 1) + 2];
                    float* c = acc[mt][nt];
                    asm volatile(
                        "mma.sync.aligned.m16n8k16.row.col.f32.bf16.bf16.f32 "
                        "{%0,%1,%2,%3}, {%4,%5,%6,%7}, {%8,%9}, {%0,%1,%2,%3};"
                        : "+f"(c[0]), "+f"(c[1]), "+f"(c[2]), "+f"(c[3])
                        : "r"(a[mt][0]), "r"(a[mt][1]), "r"(a[mt][2]), "r"(a[mt][3]),
                          "r"(b0), "r"(b1));
                }
        }
        __syncthreads();   // A/B consumed; minb[buf] visible

        // --- post-MMA: A reload on row change (A buffer now free) ---
        if (have_next && rowchg && tid == 0) {
            asm volatile("fence.proxy.async.shared::cta;" ::: "memory");
            bulk_ld(sAb, gx + (size_t)nby * BLOB, BLOB,
                    mbar0 + (uint32_t)(buf ^ 1) * 8);
        }

        // --- screen with fast-path skip ---
        float sqa0 = sqa[wy * 32 + (lane >> 2)];
        float sqa1 = sqa[wy * 32 + (lane >> 2) + 8];
        float sqa2 = sqa[wy * 32 + 16 + (lane >> 2)];
        float sqa3 = sqa[wy * 32 + 16 + (lane >> 2) + 8];

        float local = 0.0f;
        {
            float maxacc = acc[0][0][0];
#pragma unroll
            for (int mt = 0; mt < 2; mt++)
#pragma unroll
                for (int nt = 0; nt < 8; nt++)
#pragma unroll
                    for (int v = 0; v < 4; v++)
                        maxacc = fmaxf(maxacc, acc[mt][nt][v]);
            float minsqa = fminf(fminf(sqa0, sqa1), fminf(sqa2, sqa3));
            bool skip = (minsqa + minb[buf] - 2.0f * maxacc) >= SCREEN_T;
            if (!skip) {
#pragma unroll
                for (int mt = 0; mt < 2; mt++) {
#pragma unroll
                    for (int nt = 0; nt < 8; nt++) {
#pragma unroll
                        for (int v = 0; v < 4; v++) {
                            int arow = wy * 32 + mt * 16 + (lane >> 2) + 8 * (v >> 1);
                            int col  = wx * 64 + nt * 8 + (lane & 3) * 2 + (v & 1);
                            float sqav = mt ? ((v >> 1) ? sqa3 : sqa2)
                                            : ((v >> 1) ? sqa1 : sqa0);
                            float l2s = sqav + sqb[col] - 2.0f * acc[mt][nt][v];
                            if (l2s < SCREEN_T) {
                                int aa = arow0 + arow;
                                int bb = brow0 + col;
                                if (aa == bb) {
                                    local += 5.0f;   // k1=1, k0=5 at l2=0
                                } else {
                                    uint32_t pos = atomicAdd(qcount, 1u);
                                    if (pos < QCAP)
                                        queue[pos] = ((uint32_t)arow << 8) | (uint32_t)col;
                                    else
                                        local += pair_exact_scalar(aa, bb, src0, tar0,
                                                                   src1, tar1);
                                }
                            }
                        }
                    }
                }
            }
        }
        __syncthreads();

        // --- queue: warp-cooperative exact recompute ---
        uint32_t cnt = *qcount;
        if (cnt > QCAP) cnt = QCAP;
        float wq = 0.0f;
        for (uint32_t q = (uint32_t)wid; q < cnt; q += 8) {
            uint32_t e = queue[q];
            int aa = arow0 + (int)(e >> 8);
            int bb = brow0 + (int)(e & 255u);
            const float* ra1 = (aa < BSZ) ? (src1 + (size_t)aa * D1)
                                          : (tar1 + (size_t)(aa - BSZ) * D1);
            const float* rb1 = (bb < BSZ) ? (src1 + (size_t)bb * D1)
                                          : (tar1 + (size_t)(bb - BSZ) * D1);
            float4 x = ((const float4*)ra1)[lane];
            float4 y = ((const float4*)rb1)[lane];
            float dp1 = x.x * y.x + x.y * y.y + x.z * y.z + x.w * y.w;
#pragma unroll
            for (int off = 16; off; off >>= 1)
                dp1 += __shfl_xor_sync(0xffffffffu, dp1, off);
            float l21 = g_sq1[aa] + g_sq1[bb] - 2.0f * dp1;
            if (l21 < EXACT_T) {
                const float* ra0 = (aa < BSZ) ? (src0 + (size_t)aa * D0)
                                              : (tar0 + (size_t)(aa - BSZ) * D0);
                const float* rb0 = (bb < BSZ) ? (src0 + (size_t)bb * D0)
                                              : (tar0 + (size_t)(bb - BSZ) * D0);
                float dp0 = 0.0f;
#pragma unroll
                for (int itn = 0; itn < 16; itn++) {
                    float4 xx = ((const float4*)ra0)[lane + itn * 32];
                    float4 yy = ((const float4*)rb0)[lane + itn * 32];
                    dp0 += xx.x * yy.x + xx.y * yy.y + xx.z * yy.z + xx.w * yy.w;
                }
#pragma unroll
                for (int off = 16; off; off >>= 1)
                    dp0 += __shfl_xor_sync(0xffffffffu, dp0, off);
                float l20 = g_sq0[aa] + g_sq0[bb] - 2.0f * dp0;
                float k0v = 0.0f;
#pragma unroll
                for (int qq = 0; qq < 5; qq++)
                    k0v += expf(-l20 * g_inv_bw[qq]);
                if (lane == 0) wq += k0v * expf(-l21 * (1.0f / 1.68f));
            }
        }

        // --- reduce + signed/weighted accumulate ---
#pragma unroll
        for (int off = 16; off; off >>= 1)
            local += __shfl_xor_sync(0xffffffffu, local, off);
        if (lane == 0) wred[wid] = local + wq;
        __syncthreads();
        if (tid == 0) {
            float rsum = 0.0f;
#pragma unroll
            for (int i = 0; i < 8; i++) rsum += wred[i];
            if (rsum != 0.0f) {
                float w   = (bx == by) ? 1.0f : 2.0f;
                float sgn = ((by < NT / 2) == (bx < NT / 2)) ? 1.0f : -1.0f;
                atomicAdd(&g_acc, (double)(rsum * w * sgn));
            }
            *qcount = 0;      // ordered before next screen by the syncs above it
        }
        by = nby; bx = nbx;
    }

    // --- last persistent CTA writes the final scalar (fused k_out) ---
    __syncthreads();
    if (tid == 0) {
        __threadfence();
        unsigned o = atomicAdd(&g_done_tile, 1u);
        if (o == PERSIST_GRID - 1)
            out[0] = (float)(g_acc / ((double)BSZ * (double)BSZ));
    }
}

extern "C" void kernel_launch(void* const* d_in, const int* in_sizes, int n_in,
                              void* d_out, int out_size)
{
    const float* src0 = (const float*)d_in[0];
    const float* src1 = (const float*)d_in[1];
    const float* tar0 = (const float*)d_in[2];
    const float* tar1 = (const float*)d_in[3];
    float* out = (float*)d_out;

    cudaFuncSetAttribute(k_tile, cudaFuncAttributeMaxDynamicSharedMemorySize, SM_TOTAL);

    k_pre<<<256, 256>>>(src1, tar1);
    k_f0<<<dim3(8, 64), 256>>>(src0, tar0);
    k_tile<<<PERSIST_GRID, 256, SM_TOTAL>>>(src0, tar0, src1, tar1, out);
}